// round 4
// baseline (speedup 1.0000x reference)
#include <cuda_runtime.h>
#include <cuda_fp16.h>
#include <cstdint>

#define NUM_EMB 16384
#define BT      16384
#define D       64
#define N_TILE  128
#define NTILES  (NUM_EMB / N_TILE)     // 128
#define M_TILE  128
#define NCTA    (BT / M_TILE)          // 128
#define INV2048 (4.8828125e-4f)

// smem: A tokens [128 x 256B], B double buffer [2 x 128 x 256B]
#define SM_A   0
#define SM_B0  32768
#define SM_B1  65536
#define SM_TOT 98304

// ---------------- device scratch ----------------
__device__ float  g_qcb[NUM_EMB * D];      // projected codebook (fp32, for gather)
__device__ __half g_cbh[NUM_EMB * 128];    // per code: [hi(64) | lo*2048 (64)] fp16
__device__ int    g_idx[BT];
__device__ float  g_partials[128];

// ---------------- helpers ----------------
__device__ __forceinline__ uint32_t smem_u32(const void* p) {
    uint32_t a;
    asm("{ .reg .u64 t; cvta.to.shared.u64 t, %1; cvt.u32.u64 %0, t; }" : "=r"(a) : "l"(p));
    return a;
}
// 16B-chunk XOR swizzle within a 256B row
__device__ __forceinline__ uint32_t swz(uint32_t byte, uint32_t row) {
    return ((((byte) >> 4) ^ (row & 7u)) << 4) | (byte & 15u);
}

#define LDSM_X4(r0, r1, r2, r3, addr) \
    asm volatile("ldmatrix.sync.aligned.m8n8.x4.shared.b16 {%0,%1,%2,%3}, [%4];" \
                 : "=r"(r0), "=r"(r1), "=r"(r2), "=r"(r3) : "r"(addr))

#define MMA16816(c0, c1, c2, c3, a0, a1, a2, a3, b0, b1) \
    asm volatile("mma.sync.aligned.m16n8k16.row.col.f32.f16.f16.f32 " \
                 "{%0,%1,%2,%3}, {%4,%5,%6,%7}, {%8,%9}, {%0,%1,%2,%3};" \
                 : "+f"(c0), "+f"(c1), "+f"(c2), "+f"(c3) \
                 : "r"(a0), "r"(a1), "r"(a2), "r"(a3), "r"(b0), "r"(b1))

#define CP_ASYNC16(dst, src) \
    asm volatile("cp.async.cg.shared.global [%0], [%1], 16;" :: "r"(dst), "l"(src) : "memory")
#define CP_COMMIT()  asm volatile("cp.async.commit_group;" ::: "memory")
#define CP_WAIT1()   asm volatile("cp.async.wait_group 1;" ::: "memory")
#define CP_WAIT0()   asm volatile("cp.async.wait_group 0;" ::: "memory")

// ================= kPrep: project + normalize + fp16 hi/lo split =================
__global__ void __launch_bounds__(256) kPrep(const float* __restrict__ cb,
                                             const float* __restrict__ pw,
                                             const float* __restrict__ pb) {
    __shared__ float pwT[64 * 64];
    __shared__ float qs [64 * 64];
    __shared__ float rnorm[64];
    const int tid = threadIdx.x;

    for (int i = tid; i < 4096; i += 256) {
        int c = i >> 6, k = i & 63;
        pwT[k * 64 + c] = pw[i];
    }
    __syncthreads();

    const int c  = tid & 63;
    const int rg = tid >> 6;
    const float bias = pb[c];
    for (int rr = 0; rr < 16; rr++) {
        int lrow = rg * 16 + rr;
        int row  = blockIdx.x * 64 + lrow;
        const float* cbr = cb + row * 64;
        float acc = bias;
#pragma unroll
        for (int k = 0; k < 64; k++)
            acc = fmaf(__ldg(cbr + k), pwT[k * 64 + c], acc);
        qs[lrow * 64 + c] = acc;
    }
    __syncthreads();

    if (tid < 64) {
        float s = 0.f;
#pragma unroll
        for (int k = 0; k < 64; k++) {
            float v = qs[tid * 64 + k];
            s = fmaf(v, v, s);
        }
        rnorm[tid] = 1.0f / fmaxf(sqrtf(s), 1e-12f);
    }
    __syncthreads();

    const int base = blockIdx.x * 4096;
    for (int i = tid; i < 4096; i += 256) {
        float v = qs[i];
        int row = i >> 6, col = i & 63;
        g_qcb[base + i] = v;
        float cn = v * rnorm[row];
        __half hi = __float2half_rn(cn);
        float lof = (cn - __half2float(hi)) * 2048.0f;
        size_t code = (size_t)(blockIdx.x * 64 + row);
        g_cbh[code * 128 + col]      = hi;
        g_cbh[code * 128 + 64 + col] = __float2half_rn(lof);
    }
}

// ================= kMain: HMMA GEMM + fused argmax (6-way MMA ILP) =================
__global__ void __launch_bounds__(256, 1) kMain(const float* __restrict__ z,
                                                float* __restrict__ out, int out_size) {
    extern __shared__ char smem[];
    const uint32_t sb = smem_u32(smem);
    const int tid  = threadIdx.x;
    const int lane = tid & 31;
    const int w    = tid >> 5;

    // ---- token prep: normalize + hi/lo split into swizzled smem A ----
    if (tid < 128) {
        const int token = blockIdx.x * M_TILE + tid;
        const float4* z4 = (const float4*)(z + (size_t)token * D);
        float v[64];
        float s = 0.f;
#pragma unroll
        for (int j = 0; j < 16; j++) {
            float4 t = z4[j];
            v[4 * j] = t.x; v[4 * j + 1] = t.y; v[4 * j + 2] = t.z; v[4 * j + 3] = t.w;
            s += t.x * t.x + t.y * t.y + t.z * t.z + t.w * t.w;
        }
        const float inv = 1.0f / fmaxf(sqrtf(s), 1e-12f);
        const uint32_t rowbase = (uint32_t)tid * 256u;
#pragma unroll
        for (int j = 0; j < 32; j++) {
            float z0 = v[2 * j] * inv, z1 = v[2 * j + 1] * inv;
            __half h0 = __float2half_rn(z0), h1 = __float2half_rn(z1);
            float l0 = (z0 - __half2float(h0)) * 2048.0f;
            float l1 = (z1 - __half2float(h1)) * 2048.0f;
            __half2 hh = __halves2half2(h0, h1);
            __half2 ll = __halves2half2(__float2half_rn(l0), __float2half_rn(l1));
            uint32_t bhh = 4u * j;
            uint32_t bll = 128u + 4u * j;
            *(__half2*)(smem + SM_A + rowbase + swz(bhh, (uint32_t)tid)) = hh;
            *(__half2*)(smem + SM_A + rowbase + swz(bll, (uint32_t)tid)) = ll;
        }
    }

#define FILL(stage, tile_)                                                        \
    do {                                                                          \
        for (int i = 0; i < 8; i++) {                                             \
            int idx = tid + i * 256;                                              \
            uint32_t code = (uint32_t)idx >> 4;                                   \
            uint32_t ch   = (uint32_t)idx & 15u;                                  \
            uint32_t dst  = sb + (stage) + code * 256u + ((ch ^ (code & 7u)) << 4); \
            const __half* src = g_cbh + ((size_t)(tile_) * N_TILE + code) * 128 + ch * 8; \
            CP_ASYNC16(dst, src);                                                 \
        }                                                                         \
        CP_COMMIT();                                                              \
    } while (0)

    FILL(SM_B0, 0);
    FILL(SM_B1, 1);
    __syncthreads();

    // ---- load A fragments (persistent in registers) ----
    uint32_t ah[16], al[16];
    {
        const uint32_t arow = (uint32_t)(w * 16) + (uint32_t)((lane & 7) + ((lane >> 3) & 1) * 8);
        const uint32_t kx   = (uint32_t)(lane >> 4) * 16u;
        const uint32_t abase = sb + SM_A + arow * 256u;
#pragma unroll
        for (int j = 0; j < 4; j++) {
            uint32_t adh = abase + swz(32u * j + kx, arow);
            LDSM_X4(ah[4 * j], ah[4 * j + 1], ah[4 * j + 2], ah[4 * j + 3], adh);
            uint32_t adl = abase + swz(128u + 32u * j + kx, arow);
            LDSM_X4(al[4 * j], al[4 * j + 1], al[4 * j + 2], al[4 * j + 3], adl);
        }
    }

    float best0 = -3.0f, best1 = -3.0f;
    int   bidx0 = 0,     bidx1 = 0;

    const uint32_t brow_in = (uint32_t)(lane & 7);
    const uint32_t bkx     = (uint32_t)(lane >> 3) * 16u;

    for (int t = 0; t < NTILES; t++) {
        if (t + 1 < NTILES) { CP_WAIT1(); } else { CP_WAIT0(); }
        __syncthreads();
        const uint32_t Bb = sb + ((t & 1) ? SM_B1 : SM_B0);

#pragma unroll 1
        for (int nb = 0; nb < 16; nb += 2) {
            // B fragments for two adjacent 8-code blocks
            uint32_t bh[2][8], bl[2][8];
#pragma unroll
            for (int u = 0; u < 2; u++) {
                const uint32_t brow = (uint32_t)((nb + u) * 8) + brow_in;
                const uint32_t bbase = Bb + brow * 256u;
                LDSM_X4(bh[u][0], bh[u][1], bh[u][2], bh[u][3], bbase + swz(0u   + bkx, brow));
                LDSM_X4(bh[u][4], bh[u][5], bh[u][6], bh[u][7], bbase + swz(64u  + bkx, brow));
                LDSM_X4(bl[u][0], bl[u][1], bl[u][2], bl[u][3], bbase + swz(128u + bkx, brow));
                LDSM_X4(bl[u][4], bl[u][5], bl[u][6], bl[u][7], bbase + swz(192u + bkx, brow));
            }

            // 6 independent accumulator chains (c,x1,x2) x (u=0,1), each 4 deep
            float c [2][4] = {{0.f,0.f,0.f,0.f},{0.f,0.f,0.f,0.f}};
            float x1[2][4] = {{0.f,0.f,0.f,0.f},{0.f,0.f,0.f,0.f}};
            float x2[2][4] = {{0.f,0.f,0.f,0.f},{0.f,0.f,0.f,0.f}};
#pragma unroll
            for (int j = 0; j < 4; j++) {
#pragma unroll
                for (int u = 0; u < 2; u++) {
                    MMA16816(c[u][0],  c[u][1],  c[u][2],  c[u][3],
                             ah[4*j], ah[4*j+1], ah[4*j+2], ah[4*j+3], bh[u][2*j], bh[u][2*j+1]);
                    MMA16816(x1[u][0], x1[u][1], x1[u][2], x1[u][3],
                             ah[4*j], ah[4*j+1], ah[4*j+2], ah[4*j+3], bl[u][2*j], bl[u][2*j+1]);
                    MMA16816(x2[u][0], x2[u][1], x2[u][2], x2[u][3],
                             al[4*j], al[4*j+1], al[4*j+2], al[4*j+3], bh[u][2*j], bh[u][2*j+1]);
                }
            }

#pragma unroll
            for (int u = 0; u < 2; u++) {
                const int n0 = t * N_TILE + (nb + u) * 8 + (lane & 3) * 2;
                float v0 = fmaf(x1[u][0] + x2[u][0], INV2048, c[u][0]);
                float v1 = fmaf(x1[u][1] + x2[u][1], INV2048, c[u][1]);
                float v2 = fmaf(x1[u][2] + x2[u][2], INV2048, c[u][2]);
                float v3 = fmaf(x1[u][3] + x2[u][3], INV2048, c[u][3]);
                if (v0 > best0) { best0 = v0; bidx0 = n0; }
                if (v1 > best0) { best0 = v1; bidx0 = n0 + 1; }
                if (v2 > best1) { best1 = v2; bidx1 = n0; }
                if (v3 > best1) { best1 = v3; bidx1 = n0 + 1; }
            }
        }
        __syncthreads();
        if (t + 2 < NTILES) FILL(((t & 1) ? SM_B1 : SM_B0), t + 2);
    }
#undef FILL

    // ---- reduce argmax across the 4 lanes of each row quad ----
#pragma unroll
    for (int off = 1; off < 4; off <<= 1) {
        float ob = __shfl_xor_sync(0xFFFFFFFFu, best0, off);
        int   oi = __shfl_xor_sync(0xFFFFFFFFu, bidx0, off);
        if (ob > best0 || (ob == best0 && oi < bidx0)) { best0 = ob; bidx0 = oi; }
        ob = __shfl_xor_sync(0xFFFFFFFFu, best1, off);
        oi = __shfl_xor_sync(0xFFFFFFFFu, bidx1, off);
        if (ob > best1 || (ob == best1 && oi < bidx1)) { best1 = ob; bidx1 = oi; }
    }
    if ((lane & 3) == 0) {
        const int tok0 = blockIdx.x * M_TILE + w * 16 + (lane >> 2);
        const int tok1 = tok0 + 8;
        g_idx[tok0] = bidx0;
        g_idx[tok1] = bidx1;
        int off0 = BT * D + 1 + tok0;
        int off1 = BT * D + 1 + tok1;
        if (off0 < out_size) out[off0] = (float)bidx0;
        if (off1 < out_size) out[off1] = (float)bidx1;
    }
}

// ================= kC: gather quantized + partial MSE =================
__global__ void __launch_bounds__(256) kC(const float* __restrict__ z,
                                          float* __restrict__ out, int out_size) {
    __shared__ float red[256];
    const int tid = threadIdx.x;
    const float4* z4 = (const float4*)z;
    const float4* q4 = (const float4*)g_qcb;
    float4* o4 = (float4*)out;

    float ps = 0.f;
#pragma unroll
    for (int i = 0; i < 8; i++) {
        int g = blockIdx.x * 2048 + i * 256 + tid;
        int token = g >> 4;
        int idx = g_idx[token];
        float4 q = q4[idx * 16 + (g & 15)];
        float4 zz = z4[g];
        if (g * 4 + 3 < out_size) o4[g] = q;
        float dx = q.x - zz.x, dy = q.y - zz.y;
        float dz_ = q.z - zz.z, dw = q.w - zz.w;
        ps += dx * dx + dy * dy + dz_ * dz_ + dw * dw;
    }
    red[tid] = ps;
    __syncthreads();
    for (int st = 128; st > 0; st >>= 1) {
        if (tid < st) red[tid] += red[tid + st];
        __syncthreads();
    }
    if (tid == 0) g_partials[blockIdx.x] = red[0];
}

// ================= kD: finalize loss =================
__global__ void kD(float* __restrict__ out, int out_size) {
    __shared__ float red[128];
    int tid = threadIdx.x;
    red[tid] = g_partials[tid];
    __syncthreads();
    for (int st = 64; st > 0; st >>= 1) {
        if (tid < st) red[tid] += red[tid + st];
        __syncthreads();
    }
    if (tid == 0) {
        float loss = 1.25f * red[0] / (float)(BT * D);
        if (BT * D < out_size) out[BT * D] = loss;
    }
}

// ================= launch =================
extern "C" void kernel_launch(void* const* d_in, const int* in_sizes, int n_in,
                              void* d_out, int out_size) {
    const float* z  = (const float*)d_in[0];
    const float* cb = (const float*)d_in[1];
    const float* pw = (const float*)d_in[2];
    const float* pb = (const float*)d_in[3];
    // d_in[4] = scale: positive constant, cannot change argmin or any output value.
    float* out = (float*)d_out;

    cudaFuncSetAttribute(kMain, cudaFuncAttributeMaxDynamicSharedMemorySize, SM_TOT);

    kPrep<<<NUM_EMB / 64, 256>>>(cb, pw, pb);
    kMain<<<NCTA, 256, SM_TOT>>>(z, out, out_size);
    kC<<<128, 256>>>(z, out, out_size);
    kD<<<1, 128>>>(out, out_size);
}